// round 8
// baseline (speedup 1.0000x reference)
#include <cuda_runtime.h>
#include <cuda_bf16.h>

// ---------------------------------------------------------------------------
// Scratch (allocation-free: __device__ globals)
// Activations live as packed int8 in N[C/4]HW[4c] layout (one u32 = 4 channels
// of one pixel). u8 after ReLU-fq stages, s8 after pool-fq stages.
// ---------------------------------------------------------------------------
__device__ unsigned g_bufA[8 * 1024 * 1024];   // 32 MB ping (u32 words)
__device__ unsigned g_bufB[8 * 1024 * 1024];   // 32 MB pong
__device__ signed char g_wqi[52000];           // quantized int8 weights arena
__device__ unsigned g_wpk[14336];              // packed weights (u32)
__device__ float g_wscale[8];                  // per-tensor weight scales
__device__ float g_gap[2048];                  // [8,256] pooled features (float)

// byte-arena offsets (same order as wq srcs)
#define WQ_CONV1 0
#define WQ_B1DW  1728
#define WQ_B1PW  2304
#define WQ_B2DW  6400
#define WQ_B2PW  6976
#define WQ_B3DW  15168
#define WQ_B3PW  16320
#define WQ_FC    49088
// packed offsets (u32 units)
#define WP_B1PW  0
#define WP_B2PW  1024
#define WP_B3PW  3072
#define WP_C1    11264
#define WP_B1DW  11840
#define WP_B2DW  12224
#define WP_B3DW  12608

__device__ __forceinline__ float fqv(float x, float s, float lo, float hi) {
    float q = rintf(x / s);
    q = fminf(fmaxf(q, lo), hi);
    return q * s;
}

__device__ __forceinline__ void dp4a_us(int& acc, unsigned a, unsigned b) {
    asm("dp4a.u32.s32 %0, %1, %2, %3;" : "=r"(acc) : "r"(a), "r"(b), "r"(acc));
}
__device__ __forceinline__ void dp4a_ss(int& acc, unsigned a, unsigned b) {
    asm("dp4a.s32.s32 %0, %1, %2, %3;" : "=r"(acc) : "r"(a), "r"(b), "r"(acc));
}

__device__ __forceinline__ int clampi(int v, int lo, int hi) {
    return min(max(v, lo), hi);
}

// ---------------------------------------------------------------------------
// Weight quantize: int8 arena + packed pw/conv1/dw u32 + scales. 1 block/tensor.
// ---------------------------------------------------------------------------
__global__ void wq_kernel(const float* w0, const float* w1, const float* w2,
                          const float* w3, const float* w4, const float* w5,
                          const float* w6, const float* w7) {
    __shared__ float red[256];
    __shared__ signed char sq[32768];
    const float* srcs[8] = {w0, w1, w2, w3, w4, w5, w6, w7};
    const int sizes[8] = {1728, 576, 4096, 576, 8192, 1152, 32768, 2560};
    const int offs[8]  = {WQ_CONV1, WQ_B1DW, WQ_B1PW, WQ_B2DW,
                          WQ_B2PW, WQ_B3DW, WQ_B3PW, WQ_FC};
    const int cins[8]  = {0, 0, 64, 0, 64, 0, 128, 0};
    const int pwo[8]   = {-1, -1, WP_B1PW, -1, WP_B2PW, -1, WP_B3PW, -1};
    const int dwo[8]   = {-1, WP_B1DW, -1, WP_B2DW, -1, WP_B3DW, -1, -1};
    int t = blockIdx.x;
    const float* w = srcs[t];
    int n = sizes[t];

    float m = 0.0f;
    for (int i = threadIdx.x; i < n; i += 256) m = fmaxf(m, fabsf(w[i]));
    red[threadIdx.x] = m;
    __syncthreads();
    for (int s = 128; s > 0; s >>= 1) {
        if (threadIdx.x < s)
            red[threadIdx.x] = fmaxf(red[threadIdx.x], red[threadIdx.x + s]);
        __syncthreads();
    }
    float scale = red[0] / 127.0f;
    for (int i = threadIdx.x; i < n; i += 256) {
        int q = clampi(__float2int_rn(w[i] / scale), -127, 127);
        sq[i] = (signed char)q;
        g_wqi[offs[t] + i] = (signed char)q;
    }
    if (threadIdx.x == 0) g_wscale[t] = scale;
    __syncthreads();

    if (pwo[t] >= 0) {
        int CIN = cins[t], COUT = n / CIN;
        int npk = n / 4;
        for (int i = threadIdx.x; i < npk; i += 256) {
            int ic4 = i / COUT, oc = i % COUT;
            unsigned b0 = (unsigned char)sq[oc * CIN + ic4 * 4 + 0];
            unsigned b1 = (unsigned char)sq[oc * CIN + ic4 * 4 + 1];
            unsigned b2 = (unsigned char)sq[oc * CIN + ic4 * 4 + 2];
            unsigned b3 = (unsigned char)sq[oc * CIN + ic4 * 4 + 3];
            g_wpk[pwo[t] + i] = b0 | (b1 << 8) | (b2 << 16) | (b3 << 24);
        }
    }
    if (dwo[t] >= 0) {
        // dw pack: per channel c, per ky: wA=[w0,w1,w2,0], wB=[0,w0,w1,w2]
        int C = n / 9;
        for (int i = threadIdx.x; i < C * 3; i += 256) {
            int c = i / 3, ky = i % 3;
            unsigned b0 = (unsigned char)sq[c * 9 + ky * 3 + 0];
            unsigned b1 = (unsigned char)sq[c * 9 + ky * 3 + 1];
            unsigned b2 = (unsigned char)sq[c * 9 + ky * 3 + 2];
            g_wpk[dwo[t] + i * 2 + 0] = b0 | (b1 << 8) | (b2 << 16);
            g_wpk[dwo[t] + i * 2 + 1] = (b0 << 8) | (b1 << 16) | (b2 << 24);
        }
    }
    if (t == 0) {
        // conv1 pack: [oc][9 taps], bytes = [ic0, ic1, ic2, 0]
        for (int i = threadIdx.x; i < 576; i += 256) {
            int oc = i / 9, k = i % 9;
            unsigned b0 = (unsigned char)sq[oc * 27 + 0 + k];
            unsigned b1 = (unsigned char)sq[oc * 27 + 9 + k];
            unsigned b2 = (unsigned char)sq[oc * 27 + 18 + k];
            g_wpk[WP_C1 + i] = b0 | (b1 << 8) | (b2 << 16);
        }
    }
}

// ---------------------------------------------------------------------------
// conv1 (fused input fq): float x -> fq(s0,s8) packed inline -> 3x3 conv
// (3->64, pad 1) via dp4a + bias + relu + fq(s1, u8 bytes).
// Block (8,32): 32x32 tile, 4 px/thread.
// ---------------------------------------------------------------------------
__global__ void conv1_kernel(const float* __restrict__ x,
                             const float* __restrict__ bias,
                             const float* __restrict__ scales,
                             unsigned* __restrict__ out) {
    __shared__ unsigned s_pix[34 * 34];
    __shared__ unsigned s_w[576];
    __shared__ float s_b[64];
    int n = blockIdx.z;
    int x0 = blockIdx.x * 32, y0 = blockIdx.y * 32;
    int tid = threadIdx.y * 8 + threadIdx.x;
    float inv_s0 = 1.0f / scales[0];

    for (int i = tid; i < 576; i += 256) s_w[i] = g_wpk[WP_C1 + i];
    if (tid < 64) s_b[tid] = bias[tid];

    const float* xp = x + (size_t)n * 3 * 50176;
    for (int i = tid; i < 34 * 34; i += 256) {
        int ly = i / 34, lx = i % 34;
        int gy = y0 + ly - 1, gx = x0 + lx - 1;
        unsigned v = 0;
        if (gy >= 0 && gy < 224 && gx >= 0 && gx < 224) {
            const float* pb = xp + gy * 224 + gx;
            unsigned b0 = (unsigned)(clampi(__float2int_rn(pb[0] * inv_s0), -128, 127) & 0xFF);
            unsigned b1 = (unsigned)(clampi(__float2int_rn(pb[50176] * inv_s0), -128, 127) & 0xFF);
            unsigned b2 = (unsigned)(clampi(__float2int_rn(pb[100352] * inv_s0), -128, 127) & 0xFF);
            v = b0 | (b1 << 8) | (b2 << 16);
        }
        s_pix[i] = v;
    }
    __syncthreads();

    int tx = threadIdx.x, ty = threadIdx.y;
    int x4 = tx * 4;

    unsigned p[3][6];
    #pragma unroll
    for (int ky = 0; ky < 3; ky++)
        #pragma unroll
        for (int dx = 0; dx < 6; dx++)
            p[ky][dx] = s_pix[(ty + ky) * 34 + x4 + dx];

    float inv_s1 = 1.0f / scales[1];
    float A = scales[0] * g_wscale[0] * inv_s1;
    size_t obase = ((size_t)(n * 16) * 224 + (y0 + ty)) * 224 + x0 + x4;

    for (int ocg = 0; ocg < 16; ocg++) {
        int acc[4][4] = {};   // [oc-in-group][px]
        #pragma unroll
        for (int j = 0; j < 4; j++) {
            const unsigned* wp = &s_w[(ocg * 4 + j) * 9];
            #pragma unroll
            for (int ky = 0; ky < 3; ky++)
                #pragma unroll
                for (int kx = 0; kx < 3; kx++) {
                    unsigned w = wp[ky * 3 + kx];
                    dp4a_ss(acc[j][0], p[ky][kx + 0], w);
                    dp4a_ss(acc[j][1], p[ky][kx + 1], w);
                    dp4a_ss(acc[j][2], p[ky][kx + 2], w);
                    dp4a_ss(acc[j][3], p[ky][kx + 3], w);
                }
        }
        uint4 pk;
        unsigned* pw = &pk.x;
        #pragma unroll
        for (int pt = 0; pt < 4; pt++) {
            unsigned v = 0;
            #pragma unroll
            for (int j = 0; j < 4; j++) {
                float B = s_b[ocg * 4 + j] * inv_s1;
                int q = clampi(__float2int_rn(fmaf(A, (float)acc[j][pt], B)), 0, 255);
                v |= (unsigned)q << (8 * j);
            }
            pw[pt] = v;
        }
        *(uint4*)&out[obase + (size_t)ocg * 50176] = pk;
    }
}

// ---------------------------------------------------------------------------
// Depthwise 3x3 (pad 1) + bias + relu + fq(u8) via byte_perm + dp4a.
// Thread: 4 px x 4 channels. Per (row, ch): 5 PRMT + 4 dp4a.
// ---------------------------------------------------------------------------
template <bool SIGNED>
__global__ void dw_kernel(const unsigned* __restrict__ in,
                          unsigned* __restrict__ out,
                          int wpko, const float* __restrict__ bias,
                          int G, int H, int W,
                          const float* __restrict__ scales,
                          int si_in, int si_out, int wsi) {
    extern __shared__ unsigned s_dw[];  // [G*4 ch][3 ky][2] packed weight words
    int tid = threadIdx.x;
    for (int i = tid; i < G * 24; i += 256) s_dw[i] = g_wpk[wpko + i];
    __syncthreads();

    int idx = blockIdx.x * 256 + tid;
    int W4 = W >> 2;
    int x4 = (idx % W4) * 4;
    int t = idx / W4;
    int yy = t % H; t /= H;
    int g = t % G;
    int n = t / G;

    // preload packed weights for this channel group
    unsigned wA[4][3], wB[4][3];
    #pragma unroll
    for (int j = 0; j < 4; j++)
        #pragma unroll
        for (int ky = 0; ky < 3; ky++) {
            wA[j][ky] = s_dw[((g * 4 + j) * 3 + ky) * 2 + 0];
            wB[j][ky] = s_dw[((g * 4 + j) * 3 + ky) * 2 + 1];
        }

    const unsigned* p = in + (size_t)(n * G + g) * H * W;
    int acc[4][4] = {};   // [ch][px]

    #pragma unroll
    for (int ky = 0; ky < 3; ky++) {
        int gy = yy + ky - 1;
        if (gy < 0 || gy >= H) continue;
        const unsigned* rp = p + (size_t)gy * W;
        uint4 mm = *(const uint4*)&rp[x4];
        unsigned v0 = (x4 > 0) ? rp[x4 - 1] : 0u;
        unsigned v5 = (x4 + 4 < W) ? rp[x4 + 4] : 0u;
        #pragma unroll
        for (int j = 0; j < 4; j++) {
            unsigned sel = (unsigned)j | ((unsigned)(j + 4) << 4);
            unsigned t01 = __byte_perm(v0, mm.x, sel);      // [bj(v0), bj(v1)]
            unsigned t23 = __byte_perm(mm.y, mm.z, sel);    // [bj(v2), bj(v3)]
            unsigned t45 = __byte_perm(mm.w, v5, sel);      // [bj(v4), bj(v5)]
            unsigned s0 = __byte_perm(t01, t23, 0x5410);    // [x-1,x0,x1,x2]
            unsigned s1 = __byte_perm(t23, t45, 0x5410);    // [x1,x2,x3,x4]
            if (SIGNED) {
                dp4a_ss(acc[j][0], s0, wA[j][ky]);
                dp4a_ss(acc[j][1], s0, wB[j][ky]);
                dp4a_ss(acc[j][2], s1, wA[j][ky]);
                dp4a_ss(acc[j][3], s1, wB[j][ky]);
            } else {
                dp4a_us(acc[j][0], s0, wA[j][ky]);
                dp4a_us(acc[j][1], s0, wB[j][ky]);
                dp4a_us(acc[j][2], s1, wA[j][ky]);
                dp4a_us(acc[j][3], s1, wB[j][ky]);
            }
        }
    }

    float inv_o = 1.0f / scales[si_out];
    float A = scales[si_in] * g_wscale[wsi] * inv_o;
    float B[4];
    #pragma unroll
    for (int j = 0; j < 4; j++) B[j] = bias[g * 4 + j] * inv_o;

    uint4 pk;
    unsigned* pw = &pk.x;
    #pragma unroll
    for (int pp = 0; pp < 4; pp++) {
        unsigned v = 0;
        #pragma unroll
        for (int j = 0; j < 4; j++) {
            int q = clampi(__float2int_rn(fmaf(A, (float)acc[j][pp], B[j])), 0, 255);
            v |= (unsigned)q << (8 * j);
        }
        pw[pp] = v;
    }
    *(uint4*)&out[(size_t)idx * 4] = pk;
}

// ---------------------------------------------------------------------------
// Fused pointwise 1x1 + bias + relu + fq(u8) + 2x2 maxpool + requant(s8).
// Block tile: 2 rows x 64 cols (128 px); thread 4 px x 8 oc; u8 results
// staged in smem, pooled output written directly (pw tensor never hits gmem).
// ---------------------------------------------------------------------------
template <int CIN, int COUT>
__global__ void __launch_bounds__(256)
pwpool_kernel(const unsigned* __restrict__ in, unsigned* __restrict__ out,
              int wpko, const float* __restrict__ bias,
              int H, int W, const float* __restrict__ scales,
              int si_in, int si_pw, int si_pool, int wsi) {
    constexpr int CIN4 = CIN / 4;
    constexpr int COUT4 = COUT / 4;
    __shared__ unsigned s_x[CIN4 * 128];
    __shared__ unsigned s_w[CIN4 * 64];
    __shared__ unsigned s_y[16 * 128];
    int tid = threadIdx.x;
    int n = blockIdx.y;
    int SEGS = (W + 63) >> 6;
    int sx = blockIdx.x % SEGS;
    int rp = blockIdx.x / SEGS;
    int x0 = sx * 64, y0 = rp * 2;
    int OW = W >> 1, OH = H >> 1;

    // fill input tile: px 0..63 = row y0, px 64..127 = row y0+1
    for (int e = tid * 4; e < CIN4 * 128; e += 1024) {
        int ic4 = e >> 7, px = e & 127;
        int row = y0 + (px >> 6);
        int col = x0 + (px & 63);
        uint4 v = make_uint4(0, 0, 0, 0);
        if (col + 3 < W)
            v = *(const uint4*)&in[((size_t)(n * CIN4 + ic4) * H + row) * W + col];
        *(uint4*)&s_x[e] = v;
    }

    float inv_pw = 1.0f / scales[si_pw];
    float A = scales[si_in] * g_wscale[wsi] * inv_pw;
    float r = scales[si_pw] / scales[si_pool];
    int pxA = (tid & 31) * 4;
    int ocl = (tid >> 5) * 8;

    for (int oc0 = 0; oc0 < COUT; oc0 += 64) {
        __syncthreads();
        for (int e = tid; e < CIN4 * 64; e += 256) {
            int ic4 = e >> 6, o = e & 63;
            s_w[e] = g_wpk[wpko + ic4 * COUT + oc0 + o];
        }
        __syncthreads();

        int acc[8][4] = {};
        #pragma unroll 4
        for (int ic4 = 0; ic4 < CIN4; ic4++) {
            uint4 xa = *(const uint4*)&s_x[ic4 * 128 + pxA];
            uint4 wAv = *(const uint4*)&s_w[ic4 * 64 + ocl];
            uint4 wBv = *(const uint4*)&s_w[ic4 * 64 + ocl + 4];
            unsigned ws8[8] = {wAv.x, wAv.y, wAv.z, wAv.w, wBv.x, wBv.y, wBv.z, wBv.w};
            #pragma unroll
            for (int o = 0; o < 8; o++) {
                dp4a_us(acc[o][0], xa.x, ws8[o]);
                dp4a_us(acc[o][1], xa.y, ws8[o]);
                dp4a_us(acc[o][2], xa.z, ws8[o]);
                dp4a_us(acc[o][3], xa.w, ws8[o]);
            }
        }

        // pw epilogue -> u8 staged in smem
        #pragma unroll
        for (int og = 0; og < 2; og++) {
            float B[4];
            #pragma unroll
            for (int j = 0; j < 4; j++)
                B[j] = bias[oc0 + ocl + og * 4 + j] * inv_pw;
            int oc4l = (ocl >> 2) + og;   // 0..15
            #pragma unroll
            for (int pt = 0; pt < 4; pt++) {
                unsigned v = 0;
                #pragma unroll
                for (int j = 0; j < 4; j++) {
                    int q = clampi(__float2int_rn(
                        fmaf(A, (float)acc[og * 4 + j][pt], B[j])), 0, 255);
                    v |= (unsigned)q << (8 * j);
                }
                s_y[oc4l * 128 + pxA + pt] = v;
            }
        }
        __syncthreads();

        // pool 2x2 + requant to s8, write pooled tensor
        for (int i = tid; i < 16 * 32; i += 256) {
            int oc4l = i >> 5, xp = i & 31;
            int colp = (x0 >> 1) + xp;
            if (colp < OW) {
                const unsigned* yr = &s_y[oc4l * 128];
                unsigned m = __vmaxu4(__vmaxu4(yr[2 * xp], yr[2 * xp + 1]),
                                      __vmaxu4(yr[64 + 2 * xp], yr[64 + 2 * xp + 1]));
                unsigned v = 0;
                #pragma unroll
                for (int j = 0; j < 4; j++) {
                    int byte = (int)((m >> (8 * j)) & 0xFF);
                    int q = clampi(__float2int_rn((float)byte * r), -128, 127);
                    v |= (unsigned)(q & 0xFF) << (8 * j);
                }
                int oc4g = (oc0 >> 2) + oc4l;
                out[((size_t)(n * COUT4 + oc4g) * OH + rp) * OW + colp] = v;
            }
        }
    }
}

// ---------------------------------------------------------------------------
// Global avg pool 28x28 (s8 input) + fq(s[11], int8) -> g_gap floats.
// ---------------------------------------------------------------------------
__global__ void gap_kernel(const unsigned* __restrict__ in,
                           const float* __restrict__ scales) {
    __shared__ int4 red[128];
    int bc = blockIdx.x;        // n*64 + g
    const unsigned* p = in + (size_t)bc * 784;
    int s0 = 0, s1 = 0, s2 = 0, s3 = 0;
    for (int i = threadIdx.x; i < 784; i += 128) {
        unsigned v = p[i];
        s0 += (int)(v << 24) >> 24;
        s1 += (int)(v << 16) >> 24;
        s2 += (int)(v << 8) >> 24;
        s3 += (int)v >> 24;
    }
    red[threadIdx.x] = make_int4(s0, s1, s2, s3);
    __syncthreads();
    for (int s = 64; s > 0; s >>= 1) {
        if (threadIdx.x < s) {
            int4 a = red[threadIdx.x], b = red[threadIdx.x + s];
            red[threadIdx.x] = make_int4(a.x + b.x, a.y + b.y, a.z + b.z, a.w + b.w);
        }
        __syncthreads();
    }
    if (threadIdx.x == 0) {
        float s10 = scales[10], s11 = scales[11];
        int4 r = red[0];
        int n = bc >> 6, g = bc & 63;
        int sums[4] = {r.x, r.y, r.z, r.w};
        #pragma unroll
        for (int j = 0; j < 4; j++) {
            float m = s10 * (float)sums[j] / 784.0f;
            g_gap[n * 256 + g * 4 + j] = fqv(m, s11, -128.0f, 127.0f);
        }
    }
}

// ---------------------------------------------------------------------------
// FC: [8,256] @ Wq^T + b -> [8,10]
// ---------------------------------------------------------------------------
__global__ void fc_kernel(const float* __restrict__ fc_b, float* __restrict__ out) {
    int t = threadIdx.x;
    if (t < 80) {
        int n = t / 10, k = t % 10;
        float ws = g_wscale[7];
        float acc = fc_b[k];
        const signed char* w = g_wqi + WQ_FC + k * 256;
        const float* g = g_gap + n * 256;
        #pragma unroll 8
        for (int i = 0; i < 256; i++) acc += (float)w[i] * ws * g[i];
        out[t] = acc;
    }
}

// ---------------------------------------------------------------------------
// Launch
// ---------------------------------------------------------------------------
extern "C" void kernel_launch(void* const* d_in, const int* in_sizes, int n_in,
                              void* d_out, int out_size) {
    const float* x       = (const float*)d_in[0];
    const float* scales  = (const float*)d_in[1];
    const float* conv1_w = (const float*)d_in[2];
    const float* conv1_b = (const float*)d_in[3];
    const float* b1_dw_w = (const float*)d_in[4];
    const float* b1_dw_b = (const float*)d_in[5];
    const float* b1_pw_w = (const float*)d_in[6];
    const float* b1_pw_b = (const float*)d_in[7];
    const float* b2_dw_w = (const float*)d_in[8];
    const float* b2_dw_b = (const float*)d_in[9];
    const float* b2_pw_w = (const float*)d_in[10];
    const float* b2_pw_b = (const float*)d_in[11];
    const float* b3_dw_w = (const float*)d_in[12];
    const float* b3_dw_b = (const float*)d_in[13];
    const float* b3_pw_w = (const float*)d_in[14];
    const float* b3_pw_b = (const float*)d_in[15];
    const float* fc_b    = (const float*)d_in[17];
    float* out = (float*)d_out;

    unsigned *pA = nullptr, *pB = nullptr;
    cudaGetSymbolAddress((void**)&pA, g_bufA);
    cudaGetSymbolAddress((void**)&pB, g_bufB);

    // 1) quantize weights (int8 arena + packed + scales)
    wq_kernel<<<8, 256>>>(conv1_w, b1_dw_w, b1_pw_w, b2_dw_w,
                          b2_pw_w, b3_dw_w, b3_pw_w, (const float*)d_in[16]);

    // 2) conv1 (fused input fq) -> A (u8, 16 groups @224x224)
    {
        dim3 cb(8, 32), cg(7, 7, 8);
        conv1_kernel<<<cg, cb>>>(x, conv1_b, scales, pA);
    }

    // block 1: dw @224 -> pw+pool -> 16 groups @112x112
    dw_kernel<false><<<6272, 256, 16 * 24 * 4>>>(pA, pB, WP_B1DW, b1_dw_b,
                                                 16, 224, 224, scales, 1, 2, 1);
    pwpool_kernel<64, 64><<<dim3(448, 8), 256>>>(pB, pA, WP_B1PW, b1_pw_b,
                                                 224, 224, scales, 2, 3, 4, 2);

    // block 2: dw @112 -> pw+pool -> 32 groups @56x56
    dw_kernel<true><<<1568, 256, 16 * 24 * 4>>>(pA, pB, WP_B2DW, b2_dw_b,
                                                16, 112, 112, scales, 4, 5, 3);
    pwpool_kernel<64, 128><<<dim3(112, 8), 256>>>(pB, pA, WP_B2PW, b2_pw_b,
                                                  112, 112, scales, 5, 6, 7, 4);

    // block 3: dw @56 -> pw+pool -> 64 groups @28x28
    dw_kernel<true><<<784, 256, 32 * 24 * 4>>>(pA, pB, WP_B3DW, b3_dw_b,
                                               32, 56, 56, scales, 7, 8, 5);
    pwpool_kernel<128, 256><<<dim3(28, 8), 256>>>(pB, pA, WP_B3PW, b3_pw_b,
                                                  56, 56, scales, 8, 9, 10, 6);

    // head
    gap_kernel<<<512, 128>>>(pA, scales);
    fc_kernel<<<1, 128>>>(fc_b, out);
}

// round 9
// speedup vs baseline: 1.0917x; 1.0917x over previous
#include <cuda_runtime.h>
#include <cuda_bf16.h>

// ---------------------------------------------------------------------------
// Scratch (allocation-free: __device__ globals)
// Activations live as packed int8 in N[C/4]HW[4c] layout (one u32 = 4 channels
// of one pixel). u8 after ReLU-fq stages, s8 after pool-fq stages.
// ---------------------------------------------------------------------------
__device__ unsigned g_bufA[8 * 1024 * 1024];   // 32 MB ping (u32 words)
__device__ unsigned g_bufB[8 * 1024 * 1024];   // 32 MB pong
__device__ signed char g_wqi[52000];           // quantized int8 weights arena
__device__ unsigned g_wpk[14336];              // packed weights (u32)
__device__ float g_wscale[8];                  // per-tensor weight scales
__device__ float g_gap[2048];                  // [8,256] pooled features (float)

// byte-arena offsets (same order as wq srcs)
#define WQ_CONV1 0
#define WQ_B1DW  1728
#define WQ_B1PW  2304
#define WQ_B2DW  6400
#define WQ_B2PW  6976
#define WQ_B3DW  15168
#define WQ_B3PW  16320
#define WQ_FC    49088
// packed offsets (u32 units)
#define WP_B1PW  0
#define WP_B2PW  1024
#define WP_B3PW  3072
#define WP_C1    11264
#define WP_B1DW  11840
#define WP_B2DW  12224
#define WP_B3DW  12608

__device__ __forceinline__ float fqv(float x, float s, float lo, float hi) {
    float q = rintf(x / s);
    q = fminf(fmaxf(q, lo), hi);
    return q * s;
}

__device__ __forceinline__ void dp4a_us(int& acc, unsigned a, unsigned b) {
    asm("dp4a.u32.s32 %0, %1, %2, %3;" : "=r"(acc) : "r"(a), "r"(b), "r"(acc));
}
__device__ __forceinline__ void dp4a_ss(int& acc, unsigned a, unsigned b) {
    asm("dp4a.s32.s32 %0, %1, %2, %3;" : "=r"(acc) : "r"(a), "r"(b), "r"(acc));
}

// cvt.pack.sat: d = (c << 16) | (sat(a) << 8) | sat(b)
__device__ __forceinline__ unsigned pack_u8(int a, int b, unsigned c) {
    unsigned d;
    asm("cvt.pack.sat.u8.s32.b32 %0, %1, %2, %3;"
        : "=r"(d) : "r"(a), "r"(b), "r"(c));
    return d;
}
__device__ __forceinline__ unsigned pack_s8(int a, int b, unsigned c) {
    unsigned d;
    asm("cvt.pack.sat.s8.s32.b32 %0, %1, %2, %3;"
        : "=r"(d) : "r"(a), "r"(b), "r"(c));
    return d;
}

__device__ __forceinline__ int clampi(int v, int lo, int hi) {
    return min(max(v, lo), hi);
}

// ---------------------------------------------------------------------------
// Weight quantize: int8 arena + packed pw/conv1/dw u32 + scales. 1 block/tensor.
// ---------------------------------------------------------------------------
__global__ void wq_kernel(const float* w0, const float* w1, const float* w2,
                          const float* w3, const float* w4, const float* w5,
                          const float* w6, const float* w7) {
    __shared__ float red[256];
    __shared__ signed char sq[32768];
    const float* srcs[8] = {w0, w1, w2, w3, w4, w5, w6, w7};
    const int sizes[8] = {1728, 576, 4096, 576, 8192, 1152, 32768, 2560};
    const int offs[8]  = {WQ_CONV1, WQ_B1DW, WQ_B1PW, WQ_B2DW,
                          WQ_B2PW, WQ_B3DW, WQ_B3PW, WQ_FC};
    const int cins[8]  = {0, 0, 64, 0, 64, 0, 128, 0};
    const int pwo[8]   = {-1, -1, WP_B1PW, -1, WP_B2PW, -1, WP_B3PW, -1};
    const int dwo[8]   = {-1, WP_B1DW, -1, WP_B2DW, -1, WP_B3DW, -1, -1};
    int t = blockIdx.x;
    const float* w = srcs[t];
    int n = sizes[t];

    float m = 0.0f;
    for (int i = threadIdx.x; i < n; i += 256) m = fmaxf(m, fabsf(w[i]));
    red[threadIdx.x] = m;
    __syncthreads();
    for (int s = 128; s > 0; s >>= 1) {
        if (threadIdx.x < s)
            red[threadIdx.x] = fmaxf(red[threadIdx.x], red[threadIdx.x + s]);
        __syncthreads();
    }
    float scale = red[0] / 127.0f;
    for (int i = threadIdx.x; i < n; i += 256) {
        int q = clampi(__float2int_rn(w[i] / scale), -127, 127);
        sq[i] = (signed char)q;
        g_wqi[offs[t] + i] = (signed char)q;
    }
    if (threadIdx.x == 0) g_wscale[t] = scale;
    __syncthreads();

    if (pwo[t] >= 0) {
        int CIN = cins[t], COUT = n / CIN;
        int npk = n / 4;
        for (int i = threadIdx.x; i < npk; i += 256) {
            int ic4 = i / COUT, oc = i % COUT;
            unsigned b0 = (unsigned char)sq[oc * CIN + ic4 * 4 + 0];
            unsigned b1 = (unsigned char)sq[oc * CIN + ic4 * 4 + 1];
            unsigned b2 = (unsigned char)sq[oc * CIN + ic4 * 4 + 2];
            unsigned b3 = (unsigned char)sq[oc * CIN + ic4 * 4 + 3];
            g_wpk[pwo[t] + i] = b0 | (b1 << 8) | (b2 << 16) | (b3 << 24);
        }
    }
    if (dwo[t] >= 0) {
        // dw pack: per channel c, per ky: wA=[w0,w1,w2,0], wB=[0,w0,w1,w2]
        int C = n / 9;
        for (int i = threadIdx.x; i < C * 3; i += 256) {
            int c = i / 3, ky = i % 3;
            unsigned b0 = (unsigned char)sq[c * 9 + ky * 3 + 0];
            unsigned b1 = (unsigned char)sq[c * 9 + ky * 3 + 1];
            unsigned b2 = (unsigned char)sq[c * 9 + ky * 3 + 2];
            g_wpk[dwo[t] + i * 2 + 0] = b0 | (b1 << 8) | (b2 << 16);
            g_wpk[dwo[t] + i * 2 + 1] = (b0 << 8) | (b1 << 16) | (b2 << 24);
        }
    }
    if (t == 0) {
        // conv1 pack: [oc][9 taps], bytes = [ic0, ic1, ic2, 0]
        for (int i = threadIdx.x; i < 576; i += 256) {
            int oc = i / 9, k = i % 9;
            unsigned b0 = (unsigned char)sq[oc * 27 + 0 + k];
            unsigned b1 = (unsigned char)sq[oc * 27 + 9 + k];
            unsigned b2 = (unsigned char)sq[oc * 27 + 18 + k];
            g_wpk[WP_C1 + i] = b0 | (b1 << 8) | (b2 << 16);
        }
    }
}

// ---------------------------------------------------------------------------
// conv1 (fused input fq): float x -> fq(s0,s8) packed inline -> 3x3 conv
// (3->64, pad 1) via dp4a + bias + relu + fq(s1, u8 bytes).
// Block (8,32): 32x32 tile, 4 px/thread.
// ---------------------------------------------------------------------------
__global__ void conv1_kernel(const float* __restrict__ x,
                             const float* __restrict__ bias,
                             const float* __restrict__ scales,
                             unsigned* __restrict__ out) {
    __shared__ unsigned s_pix[34 * 34];
    __shared__ unsigned s_w[576];
    __shared__ float s_b[64];
    int n = blockIdx.z;
    int x0 = blockIdx.x * 32, y0 = blockIdx.y * 32;
    int tid = threadIdx.y * 8 + threadIdx.x;
    float inv_s0 = 1.0f / scales[0];

    for (int i = tid; i < 576; i += 256) s_w[i] = g_wpk[WP_C1 + i];
    if (tid < 64) s_b[tid] = bias[tid];

    const float* xp = x + (size_t)n * 3 * 50176;
    for (int i = tid; i < 34 * 34; i += 256) {
        int ly = i / 34, lx = i % 34;
        int gy = y0 + ly - 1, gx = x0 + lx - 1;
        unsigned v = 0;
        if (gy >= 0 && gy < 224 && gx >= 0 && gx < 224) {
            const float* pb = xp + gy * 224 + gx;
            int q0 = clampi(__float2int_rn(pb[0] * inv_s0), -128, 127);
            int q1 = clampi(__float2int_rn(pb[50176] * inv_s0), -128, 127);
            int q2 = clampi(__float2int_rn(pb[100352] * inv_s0), -128, 127);
            v = (unsigned)(q0 & 0xFF) | ((unsigned)(q1 & 0xFF) << 8)
              | ((unsigned)(q2 & 0xFF) << 16);
        }
        s_pix[i] = v;
    }
    __syncthreads();

    int tx = threadIdx.x, ty = threadIdx.y;
    int x4 = tx * 4;

    unsigned p[3][6];
    #pragma unroll
    for (int ky = 0; ky < 3; ky++)
        #pragma unroll
        for (int dx = 0; dx < 6; dx++)
            p[ky][dx] = s_pix[(ty + ky) * 34 + x4 + dx];

    float inv_s1 = 1.0f / scales[1];
    float A = scales[0] * g_wscale[0] * inv_s1;
    size_t obase = ((size_t)(n * 16) * 224 + (y0 + ty)) * 224 + x0 + x4;

    for (int ocg = 0; ocg < 16; ocg++) {
        int acc[4][4] = {};   // [oc-in-group][px]
        float B[4];
        #pragma unroll
        for (int j = 0; j < 4; j++) {
            B[j] = s_b[ocg * 4 + j] * inv_s1;
            const unsigned* wp = &s_w[(ocg * 4 + j) * 9];
            #pragma unroll
            for (int ky = 0; ky < 3; ky++)
                #pragma unroll
                for (int kx = 0; kx < 3; kx++) {
                    unsigned w = wp[ky * 3 + kx];
                    dp4a_ss(acc[j][0], p[ky][kx + 0], w);
                    dp4a_ss(acc[j][1], p[ky][kx + 1], w);
                    dp4a_ss(acc[j][2], p[ky][kx + 2], w);
                    dp4a_ss(acc[j][3], p[ky][kx + 3], w);
                }
        }
        uint4 pk;
        unsigned* pw = &pk.x;
        #pragma unroll
        for (int pt = 0; pt < 4; pt++) {
            int q0 = __float2int_rn(fmaf(A, (float)acc[0][pt], B[0]));
            int q1 = __float2int_rn(fmaf(A, (float)acc[1][pt], B[1]));
            int q2 = __float2int_rn(fmaf(A, (float)acc[2][pt], B[2]));
            int q3 = __float2int_rn(fmaf(A, (float)acc[3][pt], B[3]));
            pw[pt] = pack_u8(q1, q0, pack_u8(q3, q2, 0));
        }
        *(uint4*)&out[obase + (size_t)ocg * 50176] = pk;
    }
}

// ---------------------------------------------------------------------------
// Depthwise 3x3 (pad 1) + bias + relu + fq(u8) via byte_perm + dp4a.
// Thread: 4 px x 4 channels. Per (row, ch): 5 PRMT + 4 dp4a.
// ---------------------------------------------------------------------------
template <bool SIGNED>
__global__ void dw_kernel(const unsigned* __restrict__ in,
                          unsigned* __restrict__ out,
                          int wpko, const float* __restrict__ bias,
                          int G, int H, int W,
                          const float* __restrict__ scales,
                          int si_in, int si_out, int wsi) {
    extern __shared__ unsigned s_dw[];  // [G*4 ch][3 ky][2] packed weight words
    int tid = threadIdx.x;
    for (int i = tid; i < G * 24; i += 256) s_dw[i] = g_wpk[wpko + i];
    __syncthreads();

    int idx = blockIdx.x * 256 + tid;
    int W4 = W >> 2;
    int x4 = (idx % W4) * 4;
    int t = idx / W4;
    int yy = t % H; t /= H;
    int g = t % G;
    int n = t / G;

    // preload packed weights for this channel group
    unsigned wA[4][3], wB[4][3];
    #pragma unroll
    for (int j = 0; j < 4; j++)
        #pragma unroll
        for (int ky = 0; ky < 3; ky++) {
            wA[j][ky] = s_dw[((g * 4 + j) * 3 + ky) * 2 + 0];
            wB[j][ky] = s_dw[((g * 4 + j) * 3 + ky) * 2 + 1];
        }

    const unsigned* p = in + (size_t)(n * G + g) * H * W;
    int acc[4][4] = {};   // [ch][px]

    #pragma unroll
    for (int ky = 0; ky < 3; ky++) {
        int gy = yy + ky - 1;
        if (gy < 0 || gy >= H) continue;
        const unsigned* rp = p + (size_t)gy * W;
        uint4 mm = *(const uint4*)&rp[x4];
        unsigned v0 = (x4 > 0) ? rp[x4 - 1] : 0u;
        unsigned v5 = (x4 + 4 < W) ? rp[x4 + 4] : 0u;
        #pragma unroll
        for (int j = 0; j < 4; j++) {
            unsigned sel = (unsigned)j | ((unsigned)(j + 4) << 4);
            unsigned t01 = __byte_perm(v0, mm.x, sel);      // [bj(v0), bj(v1)]
            unsigned t23 = __byte_perm(mm.y, mm.z, sel);    // [bj(v2), bj(v3)]
            unsigned t45 = __byte_perm(mm.w, v5, sel);      // [bj(v4), bj(v5)]
            unsigned s0 = __byte_perm(t01, t23, 0x5410);    // [x-1,x0,x1,x2]
            unsigned s1 = __byte_perm(t23, t45, 0x5410);    // [x1,x2,x3,x4]
            if (SIGNED) {
                dp4a_ss(acc[j][0], s0, wA[j][ky]);
                dp4a_ss(acc[j][1], s0, wB[j][ky]);
                dp4a_ss(acc[j][2], s1, wA[j][ky]);
                dp4a_ss(acc[j][3], s1, wB[j][ky]);
            } else {
                dp4a_us(acc[j][0], s0, wA[j][ky]);
                dp4a_us(acc[j][1], s0, wB[j][ky]);
                dp4a_us(acc[j][2], s1, wA[j][ky]);
                dp4a_us(acc[j][3], s1, wB[j][ky]);
            }
        }
    }

    float inv_o = 1.0f / scales[si_out];
    float A = scales[si_in] * g_wscale[wsi] * inv_o;
    float B[4];
    #pragma unroll
    for (int j = 0; j < 4; j++) B[j] = bias[g * 4 + j] * inv_o;

    uint4 pk;
    unsigned* pw = &pk.x;
    #pragma unroll
    for (int pp = 0; pp < 4; pp++) {
        int q0 = __float2int_rn(fmaf(A, (float)acc[0][pp], B[0]));
        int q1 = __float2int_rn(fmaf(A, (float)acc[1][pp], B[1]));
        int q2 = __float2int_rn(fmaf(A, (float)acc[2][pp], B[2]));
        int q3 = __float2int_rn(fmaf(A, (float)acc[3][pp], B[3]));
        pw[pp] = pack_u8(q1, q0, pack_u8(q3, q2, 0));
    }
    *(uint4*)&out[(size_t)idx * 4] = pk;
}

// ---------------------------------------------------------------------------
// Pointwise 1x1 (CIN->COUT) via dp4a + bias + relu + fq(u8).
// Block tile: 128 px x 64 oc; thread 4 px x 8 oc.
// ---------------------------------------------------------------------------
template <int CIN, int COUT>
__global__ void __launch_bounds__(256)
pw_kernel(const unsigned* __restrict__ in, unsigned* __restrict__ out,
          int wpko, const float* __restrict__ bias,
          int HW, const float* __restrict__ scales,
          int si_in, int si_out, int wsi) {
    constexpr int CIN4 = CIN / 4;
    __shared__ unsigned s_x[CIN4 * 128];
    __shared__ unsigned s_w[CIN4 * 64];
    int tid = threadIdx.x;
    int n = blockIdx.y;
    int hw0 = blockIdx.x * 128;

    for (int e = tid * 4; e < CIN4 * 128; e += 1024) {
        int ic4 = e >> 7, pix = e & 127;
        *(uint4*)&s_x[e] =
            *(const uint4*)&in[(size_t)(n * CIN4 + ic4) * HW + hw0 + pix];
    }

    float inv_o = 1.0f / scales[si_out];
    float A = scales[si_in] * g_wscale[wsi] * inv_o;
    int pxA = (tid & 31) * 4;
    int ocl = (tid >> 5) * 8;
    bool ok = (hw0 + pxA) < HW;

    for (int oc0 = 0; oc0 < COUT; oc0 += 64) {
        __syncthreads();
        for (int e = tid; e < CIN4 * 64; e += 256) {
            int ic4 = e >> 6, o = e & 63;
            s_w[e] = g_wpk[wpko + ic4 * COUT + oc0 + o];
        }
        __syncthreads();

        int acc[8][4] = {};
        #pragma unroll 4
        for (int ic4 = 0; ic4 < CIN4; ic4++) {
            uint4 xa = *(const uint4*)&s_x[ic4 * 128 + pxA];
            uint4 wAv = *(const uint4*)&s_w[ic4 * 64 + ocl];
            uint4 wBv = *(const uint4*)&s_w[ic4 * 64 + ocl + 4];
            unsigned ws8[8] = {wAv.x, wAv.y, wAv.z, wAv.w, wBv.x, wBv.y, wBv.z, wBv.w};
            #pragma unroll
            for (int o = 0; o < 8; o++) {
                dp4a_us(acc[o][0], xa.x, ws8[o]);
                dp4a_us(acc[o][1], xa.y, ws8[o]);
                dp4a_us(acc[o][2], xa.z, ws8[o]);
                dp4a_us(acc[o][3], xa.w, ws8[o]);
            }
        }

        if (ok) {
            #pragma unroll
            for (int og = 0; og < 2; og++) {
                float B[4];
                #pragma unroll
                for (int j = 0; j < 4; j++)
                    B[j] = bias[oc0 + ocl + og * 4 + j] * inv_o;
                int oc4 = (oc0 + ocl) / 4 + og;
                size_t obase = (size_t)(n * (COUT / 4) + oc4) * HW + hw0;
                uint4 pk;
                unsigned* pw = &pk.x;
                #pragma unroll
                for (int pt = 0; pt < 4; pt++) {
                    int q0 = __float2int_rn(fmaf(A, (float)acc[og * 4 + 0][pt], B[0]));
                    int q1 = __float2int_rn(fmaf(A, (float)acc[og * 4 + 1][pt], B[1]));
                    int q2 = __float2int_rn(fmaf(A, (float)acc[og * 4 + 2][pt], B[2]));
                    int q3 = __float2int_rn(fmaf(A, (float)acc[og * 4 + 3][pt], B[3]));
                    pw[pt] = pack_u8(q1, q0, pack_u8(q3, q2, 0));
                }
                *(uint4*)&out[obase + pxA] = pk;
            }
        }
    }
}

// ---------------------------------------------------------------------------
// 2x2 maxpool stride 2 (per-byte vmax on u8) + requant to s8.
// ---------------------------------------------------------------------------
__global__ void pool_kernel(const unsigned* __restrict__ in,
                            unsigned* __restrict__ out,
                            int G, int H, int W,
                            const float* __restrict__ scales,
                            int si_in, int si_out) {
    int OH = H >> 1, OW = W >> 1, OW2 = OW >> 1;
    int idx = blockIdx.x * 256 + threadIdx.x;
    int ox = (idx % OW2) * 2;
    int t = idx / OW2;
    int oy = t % OH; t /= OH;
    int g = t % G;
    int n = t / G;

    const unsigned* p = in + ((size_t)(n * G + g) * H + oy * 2) * W + ox * 2;
    uint4 a = *(const uint4*)p;
    uint4 b = *(const uint4*)(p + W);
    unsigned m0 = __vmaxu4(__vmaxu4(a.x, a.y), __vmaxu4(b.x, b.y));
    unsigned m1 = __vmaxu4(__vmaxu4(a.z, a.w), __vmaxu4(b.z, b.w));

    float r = scales[si_in] / scales[si_out];
    uint2 pk;
    unsigned mm[2] = {m0, m1};
    unsigned* pw = &pk.x;
    #pragma unroll
    for (int p2 = 0; p2 < 2; p2++) {
        int q0 = __float2int_rn((float)((mm[p2]) & 0xFF) * r);
        int q1 = __float2int_rn((float)((mm[p2] >> 8) & 0xFF) * r);
        int q2 = __float2int_rn((float)((mm[p2] >> 16) & 0xFF) * r);
        int q3 = __float2int_rn((float)((mm[p2] >> 24) & 0xFF) * r);
        pw[p2] = pack_s8(q1, q0, pack_s8(q3, q2, 0));
    }
    out[((size_t)(n * G + g) * OH + oy) * OW + ox] = pk.x;
    out[((size_t)(n * G + g) * OH + oy) * OW + ox + 1] = pk.y;
}

// ---------------------------------------------------------------------------
// Global avg pool 28x28 (s8 input) + fq(s[11], int8) -> g_gap floats.
// ---------------------------------------------------------------------------
__global__ void gap_kernel(const unsigned* __restrict__ in,
                           const float* __restrict__ scales) {
    __shared__ int4 red[128];
    int bc = blockIdx.x;        // n*64 + g
    const unsigned* p = in + (size_t)bc * 784;
    int s0 = 0, s1 = 0, s2 = 0, s3 = 0;
    for (int i = threadIdx.x; i < 784; i += 128) {
        unsigned v = p[i];
        s0 += (int)(v << 24) >> 24;
        s1 += (int)(v << 16) >> 24;
        s2 += (int)(v << 8) >> 24;
        s3 += (int)v >> 24;
    }
    red[threadIdx.x] = make_int4(s0, s1, s2, s3);
    __syncthreads();
    for (int s = 64; s > 0; s >>= 1) {
        if (threadIdx.x < s) {
            int4 a = red[threadIdx.x], b = red[threadIdx.x + s];
            red[threadIdx.x] = make_int4(a.x + b.x, a.y + b.y, a.z + b.z, a.w + b.w);
        }
        __syncthreads();
    }
    if (threadIdx.x == 0) {
        float s10 = scales[10], s11 = scales[11];
        int4 r = red[0];
        int n = bc >> 6, g = bc & 63;
        int sums[4] = {r.x, r.y, r.z, r.w};
        #pragma unroll
        for (int j = 0; j < 4; j++) {
            float m = s10 * (float)sums[j] / 784.0f;
            g_gap[n * 256 + g * 4 + j] = fqv(m, s11, -128.0f, 127.0f);
        }
    }
}

// ---------------------------------------------------------------------------
// FC: [8,256] @ Wq^T + b -> [8,10]
// ---------------------------------------------------------------------------
__global__ void fc_kernel(const float* __restrict__ fc_b, float* __restrict__ out) {
    int t = threadIdx.x;
    if (t < 80) {
        int n = t / 10, k = t % 10;
        float ws = g_wscale[7];
        float acc = fc_b[k];
        const signed char* w = g_wqi + WQ_FC + k * 256;
        const float* g = g_gap + n * 256;
        #pragma unroll 8
        for (int i = 0; i < 256; i++) acc += (float)w[i] * ws * g[i];
        out[t] = acc;
    }
}

// ---------------------------------------------------------------------------
// Launch
// ---------------------------------------------------------------------------
extern "C" void kernel_launch(void* const* d_in, const int* in_sizes, int n_in,
                              void* d_out, int out_size) {
    const float* x       = (const float*)d_in[0];
    const float* scales  = (const float*)d_in[1];
    const float* conv1_w = (const float*)d_in[2];
    const float* conv1_b = (const float*)d_in[3];
    const float* b1_dw_w = (const float*)d_in[4];
    const float* b1_dw_b = (const float*)d_in[5];
    const float* b1_pw_w = (const float*)d_in[6];
    const float* b1_pw_b = (const float*)d_in[7];
    const float* b2_dw_w = (const float*)d_in[8];
    const float* b2_dw_b = (const float*)d_in[9];
    const float* b2_pw_w = (const float*)d_in[10];
    const float* b2_pw_b = (const float*)d_in[11];
    const float* b3_dw_w = (const float*)d_in[12];
    const float* b3_dw_b = (const float*)d_in[13];
    const float* b3_pw_w = (const float*)d_in[14];
    const float* b3_pw_b = (const float*)d_in[15];
    const float* fc_b    = (const float*)d_in[17];
    float* out = (float*)d_out;

    unsigned *pA = nullptr, *pB = nullptr;
    cudaGetSymbolAddress((void**)&pA, g_bufA);
    cudaGetSymbolAddress((void**)&pB, g_bufB);

    // 1) quantize weights (int8 arena + packed + scales)
    wq_kernel<<<8, 256>>>(conv1_w, b1_dw_w, b1_pw_w, b2_dw_w,
                          b2_pw_w, b3_dw_w, b3_pw_w, (const float*)d_in[16]);

    // 2) conv1 (fused input fq) -> A (u8, 16 groups @224x224)
    {
        dim3 cb(8, 32), cg(7, 7, 8);
        conv1_kernel<<<cg, cb>>>(x, conv1_b, scales, pA);
    }

    // block 1 @ 224x224, C=64 (G=16)
    dw_kernel<false><<<6272, 256, 16 * 24 * 4>>>(pA, pB, WP_B1DW, b1_dw_b,
                                                 16, 224, 224, scales, 1, 2, 1);
    pw_kernel<64, 64><<<dim3(392, 8), 256>>>(pB, pA, WP_B1PW, b1_pw_b,
                                             50176, scales, 2, 3, 2);
    pool_kernel<<<3136, 256>>>(pA, pB, 16, 224, 224, scales, 3, 4);

    // block 2 @ 112x112, 64 -> 128
    dw_kernel<true><<<1568, 256, 16 * 24 * 4>>>(pB, pA, WP_B2DW, b2_dw_b,
                                                16, 112, 112, scales, 4, 5, 3);
    pw_kernel<64, 128><<<dim3(98, 8), 256>>>(pA, pB, WP_B2PW, b2_pw_b,
                                             12544, scales, 5, 6, 4);
    pool_kernel<<<1568, 256>>>(pB, pA, 32, 112, 112, scales, 6, 7);

    // block 3 @ 56x56, 128 -> 256
    dw_kernel<true><<<784, 256, 32 * 24 * 4>>>(pA, pB, WP_B3DW, b3_dw_b,
                                               32, 56, 56, scales, 7, 8, 5);
    pw_kernel<128, 256><<<dim3(25, 8), 256>>>(pB, pA, WP_B3PW, b3_pw_b,
                                              3136, scales, 8, 9, 6);
    pool_kernel<<<784, 256>>>(pA, pB, 64, 56, 56, scales, 9, 10);

    // head
    gap_kernel<<<512, 128>>>(pB, scales);
    fc_kernel<<<1, 128>>>(fc_b, out);
}

// round 10
// speedup vs baseline: 1.2997x; 1.1905x over previous
#include <cuda_runtime.h>
#include <cuda_bf16.h>

// ---------------------------------------------------------------------------
// Scratch (allocation-free: __device__ globals)
// Activations live as packed int8 in N[C/4]HW[4c] layout (one u32 = 4 channels
// of one pixel). u8 after ReLU-fq stages, s8 after pool-fq stages.
// ---------------------------------------------------------------------------
__device__ unsigned g_bufA[8 * 1024 * 1024];   // 32 MB ping (u32 words)
__device__ unsigned g_bufB[8 * 1024 * 1024];   // 32 MB pong
__device__ signed char g_wqi[52000];           // quantized int8 weights arena
__device__ unsigned g_wpk[14336];              // packed weights (u32)
__device__ float g_wscale[8];                  // per-tensor weight scales
__device__ float g_gap[2048];                  // [8,256] pooled features (float)

// byte-arena offsets (same order as wq srcs)
#define WQ_CONV1 0
#define WQ_B1DW  1728
#define WQ_B1PW  2304
#define WQ_B2DW  6400
#define WQ_B2PW  6976
#define WQ_B3DW  15168
#define WQ_B3PW  16320
#define WQ_FC    49088
// packed offsets (u32 units)
#define WP_B1PW  0
#define WP_B2PW  1024
#define WP_B3PW  3072
#define WP_C1    11264
#define WP_B1DW  11840
#define WP_B2DW  12224
#define WP_B3DW  12608

__device__ __forceinline__ float fqv(float x, float s, float lo, float hi) {
    float q = rintf(x / s);
    q = fminf(fmaxf(q, lo), hi);
    return q * s;
}

__device__ __forceinline__ void dp4a_us(int& acc, unsigned a, unsigned b) {
    asm("dp4a.u32.s32 %0, %1, %2, %3;" : "=r"(acc) : "r"(a), "r"(b), "r"(acc));
}
__device__ __forceinline__ void dp4a_ss(int& acc, unsigned a, unsigned b) {
    asm("dp4a.s32.s32 %0, %1, %2, %3;" : "=r"(acc) : "r"(a), "r"(b), "r"(acc));
}

// cvt.pack.sat: d = (c << 16) | (sat(a) << 8) | sat(b)
__device__ __forceinline__ unsigned pack_u8(int a, int b, unsigned c) {
    unsigned d;
    asm("cvt.pack.sat.u8.s32.b32 %0, %1, %2, %3;"
        : "=r"(d) : "r"(a), "r"(b), "r"(c));
    return d;
}
__device__ __forceinline__ unsigned pack_s8(int a, int b, unsigned c) {
    unsigned d;
    asm("cvt.pack.sat.s8.s32.b32 %0, %1, %2, %3;"
        : "=r"(d) : "r"(a), "r"(b), "r"(c));
    return d;
}

__device__ __forceinline__ int clampi(int v, int lo, int hi) {
    return min(max(v, lo), hi);
}

// ---------------------------------------------------------------------------
// Weight quantize: int8 arena + packed pw/conv1/dw u32 + scales. 1 block/tensor.
// ---------------------------------------------------------------------------
__global__ void wq_kernel(const float* w0, const float* w1, const float* w2,
                          const float* w3, const float* w4, const float* w5,
                          const float* w6, const float* w7) {
    __shared__ float red[256];
    __shared__ signed char sq[32768];
    const float* srcs[8] = {w0, w1, w2, w3, w4, w5, w6, w7};
    const int sizes[8] = {1728, 576, 4096, 576, 8192, 1152, 32768, 2560};
    const int offs[8]  = {WQ_CONV1, WQ_B1DW, WQ_B1PW, WQ_B2DW,
                          WQ_B2PW, WQ_B3DW, WQ_B3PW, WQ_FC};
    const int cins[8]  = {0, 0, 64, 0, 64, 0, 128, 0};
    const int pwo[8]   = {-1, -1, WP_B1PW, -1, WP_B2PW, -1, WP_B3PW, -1};
    const int dwo[8]   = {-1, WP_B1DW, -1, WP_B2DW, -1, WP_B3DW, -1, -1};
    int t = blockIdx.x;
    const float* w = srcs[t];
    int n = sizes[t];

    float m = 0.0f;
    for (int i = threadIdx.x; i < n; i += 256) m = fmaxf(m, fabsf(w[i]));
    red[threadIdx.x] = m;
    __syncthreads();
    for (int s = 128; s > 0; s >>= 1) {
        if (threadIdx.x < s)
            red[threadIdx.x] = fmaxf(red[threadIdx.x], red[threadIdx.x + s]);
        __syncthreads();
    }
    float scale = red[0] / 127.0f;
    for (int i = threadIdx.x; i < n; i += 256) {
        int q = clampi(__float2int_rn(w[i] / scale), -127, 127);
        sq[i] = (signed char)q;
        g_wqi[offs[t] + i] = (signed char)q;
    }
    if (threadIdx.x == 0) g_wscale[t] = scale;
    __syncthreads();

    if (pwo[t] >= 0) {
        int CIN = cins[t], COUT = n / CIN;
        int npk = n / 4;
        for (int i = threadIdx.x; i < npk; i += 256) {
            int ic4 = i / COUT, oc = i % COUT;
            unsigned b0 = (unsigned char)sq[oc * CIN + ic4 * 4 + 0];
            unsigned b1 = (unsigned char)sq[oc * CIN + ic4 * 4 + 1];
            unsigned b2 = (unsigned char)sq[oc * CIN + ic4 * 4 + 2];
            unsigned b3 = (unsigned char)sq[oc * CIN + ic4 * 4 + 3];
            g_wpk[pwo[t] + i] = b0 | (b1 << 8) | (b2 << 16) | (b3 << 24);
        }
    }
    if (dwo[t] >= 0) {
        // dw pack: per channel c, per ky: wA=[w0,w1,w2,0], wB=[0,w0,w1,w2]
        int C = n / 9;
        for (int i = threadIdx.x; i < C * 3; i += 256) {
            int c = i / 3, ky = i % 3;
            unsigned b0 = (unsigned char)sq[c * 9 + ky * 3 + 0];
            unsigned b1 = (unsigned char)sq[c * 9 + ky * 3 + 1];
            unsigned b2 = (unsigned char)sq[c * 9 + ky * 3 + 2];
            g_wpk[dwo[t] + i * 2 + 0] = b0 | (b1 << 8) | (b2 << 16);
            g_wpk[dwo[t] + i * 2 + 1] = (b0 << 8) | (b1 << 16) | (b2 << 24);
        }
    }
    if (t == 0) {
        // conv1 pack: [oc][9 taps], bytes = [ic0, ic1, ic2, 0]
        for (int i = threadIdx.x; i < 576; i += 256) {
            int oc = i / 9, k = i % 9;
            unsigned b0 = (unsigned char)sq[oc * 27 + 0 + k];
            unsigned b1 = (unsigned char)sq[oc * 27 + 9 + k];
            unsigned b2 = (unsigned char)sq[oc * 27 + 18 + k];
            g_wpk[WP_C1 + i] = b0 | (b1 << 8) | (b2 << 16);
        }
    }
}

// ---------------------------------------------------------------------------
// conv1 (fused input fq): float x -> fq(s0,s8) packed inline -> 3x3 conv
// (3->64, pad 1) via dp4a + bias + relu + fq(s1, u8 bytes).
// Block (8,32): 32x32 tile, 4 px/thread.
// ---------------------------------------------------------------------------
__global__ void conv1_kernel(const float* __restrict__ x,
                             const float* __restrict__ bias,
                             const float* __restrict__ scales,
                             unsigned* __restrict__ out) {
    __shared__ unsigned s_pix[34 * 34];
    __shared__ unsigned s_w[576];
    __shared__ float s_b[64];
    int n = blockIdx.z;
    int x0 = blockIdx.x * 32, y0 = blockIdx.y * 32;
    int tid = threadIdx.y * 8 + threadIdx.x;
    float inv_s0 = 1.0f / scales[0];

    for (int i = tid; i < 576; i += 256) s_w[i] = g_wpk[WP_C1 + i];
    if (tid < 64) s_b[tid] = bias[tid];

    const float* xp = x + (size_t)n * 3 * 50176;
    for (int i = tid; i < 34 * 34; i += 256) {
        int ly = i / 34, lx = i % 34;
        int gy = y0 + ly - 1, gx = x0 + lx - 1;
        unsigned v = 0;
        if (gy >= 0 && gy < 224 && gx >= 0 && gx < 224) {
            const float* pb = xp + gy * 224 + gx;
            int q0 = clampi(__float2int_rn(pb[0] * inv_s0), -128, 127);
            int q1 = clampi(__float2int_rn(pb[50176] * inv_s0), -128, 127);
            int q2 = clampi(__float2int_rn(pb[100352] * inv_s0), -128, 127);
            v = (unsigned)(q0 & 0xFF) | ((unsigned)(q1 & 0xFF) << 8)
              | ((unsigned)(q2 & 0xFF) << 16);
        }
        s_pix[i] = v;
    }
    __syncthreads();

    int tx = threadIdx.x, ty = threadIdx.y;
    int x4 = tx * 4;

    unsigned p[3][6];
    #pragma unroll
    for (int ky = 0; ky < 3; ky++)
        #pragma unroll
        for (int dx = 0; dx < 6; dx++)
            p[ky][dx] = s_pix[(ty + ky) * 34 + x4 + dx];

    float inv_s1 = 1.0f / scales[1];
    float A = scales[0] * g_wscale[0] * inv_s1;
    size_t obase = ((size_t)(n * 16) * 224 + (y0 + ty)) * 224 + x0 + x4;

    for (int ocg = 0; ocg < 16; ocg++) {
        int acc[4][4] = {};   // [oc-in-group][px]
        float B[4];
        #pragma unroll
        for (int j = 0; j < 4; j++) {
            B[j] = s_b[ocg * 4 + j] * inv_s1;
            const unsigned* wp = &s_w[(ocg * 4 + j) * 9];
            #pragma unroll
            for (int ky = 0; ky < 3; ky++)
                #pragma unroll
                for (int kx = 0; kx < 3; kx++) {
                    unsigned w = wp[ky * 3 + kx];
                    dp4a_ss(acc[j][0], p[ky][kx + 0], w);
                    dp4a_ss(acc[j][1], p[ky][kx + 1], w);
                    dp4a_ss(acc[j][2], p[ky][kx + 2], w);
                    dp4a_ss(acc[j][3], p[ky][kx + 3], w);
                }
        }
        uint4 pk;
        unsigned* pw = &pk.x;
        #pragma unroll
        for (int pt = 0; pt < 4; pt++) {
            int q0 = __float2int_rn(fmaf(A, (float)acc[0][pt], B[0]));
            int q1 = __float2int_rn(fmaf(A, (float)acc[1][pt], B[1]));
            int q2 = __float2int_rn(fmaf(A, (float)acc[2][pt], B[2]));
            int q3 = __float2int_rn(fmaf(A, (float)acc[3][pt], B[3]));
            pw[pt] = pack_u8(q1, q0, pack_u8(q3, q2, 0));
        }
        *(uint4*)&out[obase + (size_t)ocg * 50176] = pk;
    }
}

// ---------------------------------------------------------------------------
// Depthwise 3x3 (pad 1) + bias + relu + fq(u8) via byte_perm + dp4a.
// Thread: 4 px x 4 channels. Per (row, ch): 5 PRMT + 4 dp4a.
// ---------------------------------------------------------------------------
template <bool SIGNED>
__global__ void dw_kernel(const unsigned* __restrict__ in,
                          unsigned* __restrict__ out,
                          int wpko, const float* __restrict__ bias,
                          int G, int H, int W,
                          const float* __restrict__ scales,
                          int si_in, int si_out, int wsi) {
    extern __shared__ unsigned s_dw[];  // [G*4 ch][3 ky][2] packed weight words
    int tid = threadIdx.x;
    for (int i = tid; i < G * 24; i += 256) s_dw[i] = g_wpk[wpko + i];
    __syncthreads();

    int idx = blockIdx.x * 256 + tid;
    int W4 = W >> 2;
    int x4 = (idx % W4) * 4;
    int t = idx / W4;
    int yy = t % H; t /= H;
    int g = t % G;
    int n = t / G;

    // preload packed weights for this channel group
    unsigned wA[4][3], wB[4][3];
    #pragma unroll
    for (int j = 0; j < 4; j++)
        #pragma unroll
        for (int ky = 0; ky < 3; ky++) {
            wA[j][ky] = s_dw[((g * 4 + j) * 3 + ky) * 2 + 0];
            wB[j][ky] = s_dw[((g * 4 + j) * 3 + ky) * 2 + 1];
        }

    const unsigned* p = in + (size_t)(n * G + g) * H * W;
    int acc[4][4] = {};   // [ch][px]

    #pragma unroll
    for (int ky = 0; ky < 3; ky++) {
        int gy = yy + ky - 1;
        if (gy < 0 || gy >= H) continue;
        const unsigned* rp = p + (size_t)gy * W;
        uint4 mm = *(const uint4*)&rp[x4];
        unsigned v0 = (x4 > 0) ? rp[x4 - 1] : 0u;
        unsigned v5 = (x4 + 4 < W) ? rp[x4 + 4] : 0u;
        #pragma unroll
        for (int j = 0; j < 4; j++) {
            unsigned sel = (unsigned)j | ((unsigned)(j + 4) << 4);
            unsigned t01 = __byte_perm(v0, mm.x, sel);      // [bj(v0), bj(v1)]
            unsigned t23 = __byte_perm(mm.y, mm.z, sel);    // [bj(v2), bj(v3)]
            unsigned t45 = __byte_perm(mm.w, v5, sel);      // [bj(v4), bj(v5)]
            unsigned s0 = __byte_perm(t01, t23, 0x5410);    // [x-1,x0,x1,x2]
            unsigned s1 = __byte_perm(t23, t45, 0x5410);    // [x1,x2,x3,x4]
            if (SIGNED) {
                dp4a_ss(acc[j][0], s0, wA[j][ky]);
                dp4a_ss(acc[j][1], s0, wB[j][ky]);
                dp4a_ss(acc[j][2], s1, wA[j][ky]);
                dp4a_ss(acc[j][3], s1, wB[j][ky]);
            } else {
                dp4a_us(acc[j][0], s0, wA[j][ky]);
                dp4a_us(acc[j][1], s0, wB[j][ky]);
                dp4a_us(acc[j][2], s1, wA[j][ky]);
                dp4a_us(acc[j][3], s1, wB[j][ky]);
            }
        }
    }

    float inv_o = 1.0f / scales[si_out];
    float A = scales[si_in] * g_wscale[wsi] * inv_o;
    float B[4];
    #pragma unroll
    for (int j = 0; j < 4; j++) B[j] = bias[g * 4 + j] * inv_o;

    uint4 pk;
    unsigned* pw = &pk.x;
    #pragma unroll
    for (int pp = 0; pp < 4; pp++) {
        int q0 = __float2int_rn(fmaf(A, (float)acc[0][pp], B[0]));
        int q1 = __float2int_rn(fmaf(A, (float)acc[1][pp], B[1]));
        int q2 = __float2int_rn(fmaf(A, (float)acc[2][pp], B[2]));
        int q3 = __float2int_rn(fmaf(A, (float)acc[3][pp], B[3]));
        pw[pp] = pack_u8(q1, q0, pack_u8(q3, q2, 0));
    }
    *(uint4*)&out[(size_t)idx * 4] = pk;
}

// ---------------------------------------------------------------------------
// Pointwise 1x1 (CIN->COUT) on tensor cores: mma.sync m16n8k32 u8*s8->s32,
// + bias + relu + fq(u8). Block: 8 warps, tile 128 px x 64 oc per chunk.
//   A frag (16px x 32ic):  s_x[ic4][px] words  (our native activation layout)
//   B frag (32ic x 8oc):   s_w[ic4][oc] words  (our native weight layout)
// Epilogue requant -> u8 staged in s_y[px][oc], then coalesced repack.
// ---------------------------------------------------------------------------
template <int CIN, int COUT>
__global__ void __launch_bounds__(256)
pw_kernel(const unsigned* __restrict__ in, unsigned* __restrict__ out,
          int wpko, const float* __restrict__ bias,
          int HW, const float* __restrict__ scales,
          int si_in, int si_out, int wsi) {
    constexpr int CIN4 = CIN / 4;
    constexpr int COUT4 = COUT / 4;
    constexpr int KCH = CIN / 32;
    constexpr int SX = 136;   // s_x row stride in words (8 mod 32 -> no conflicts)
    constexpr int SW = 72;    // s_w row stride in words
    __shared__ unsigned s_x[CIN4 * SX];
    __shared__ unsigned s_w[CIN4 * SW];
    __shared__ unsigned char s_y[128 * 68];
    __shared__ float s_bias[64];

    int tid = threadIdx.x;
    int lane = tid & 31, wid = tid >> 5;
    int tig = lane & 3, gid = lane >> 2;
    int n = blockIdx.y;
    int hw0 = blockIdx.x * 128;
    int px0 = wid * 16;

    for (int e = tid * 4; e < CIN4 * 128; e += 1024) {
        int ic4 = e >> 7, pix = e & 127;
        *(uint4*)&s_x[ic4 * SX + pix] =
            *(const uint4*)&in[(size_t)(n * CIN4 + ic4) * HW + hw0 + pix];
    }

    float inv_o = 1.0f / scales[si_out];
    float A = scales[si_in] * g_wscale[wsi] * inv_o;

    for (int oc0 = 0; oc0 < COUT; oc0 += 64) {
        __syncthreads();   // s_x ready (first iter); prev repack done
        for (int e = tid; e < CIN4 * 64; e += 256) {
            int ic4 = e >> 6, o = e & 63;
            s_w[ic4 * SW + o] = g_wpk[wpko + ic4 * COUT + oc0 + o];
        }
        if (tid < 64) s_bias[tid] = bias[oc0 + tid] * inv_o;
        __syncthreads();

        int d[8][4] = {};
        #pragma unroll
        for (int c = 0; c < KCH; c++) {
            unsigned a0 = s_x[(8 * c + tig) * SX + px0 + gid];
            unsigned a1 = s_x[(8 * c + tig) * SX + px0 + gid + 8];
            unsigned a2 = s_x[(8 * c + 4 + tig) * SX + px0 + gid];
            unsigned a3 = s_x[(8 * c + 4 + tig) * SX + px0 + gid + 8];
            #pragma unroll
            for (int nb = 0; nb < 8; nb++) {
                unsigned b0 = s_w[(8 * c + tig) * SW + nb * 8 + gid];
                unsigned b1 = s_w[(8 * c + 4 + tig) * SW + nb * 8 + gid];
                asm("mma.sync.aligned.m16n8k32.row.col.s32.u8.s8.s32 "
                    "{%0,%1,%2,%3}, {%4,%5,%6,%7}, {%8,%9}, {%0,%1,%2,%3};"
                    : "+r"(d[nb][0]), "+r"(d[nb][1]), "+r"(d[nb][2]), "+r"(d[nb][3])
                    : "r"(a0), "r"(a1), "r"(a2), "r"(a3), "r"(b0), "r"(b1));
            }
        }

        // requant + relu (u8 saturate) -> staging tile s_y[px][oc]
        #pragma unroll
        for (int nb = 0; nb < 8; nb++) {
            float B0 = s_bias[nb * 8 + 2 * tig];
            float B1 = s_bias[nb * 8 + 2 * tig + 1];
            int q00 = __float2int_rn(fmaf(A, (float)d[nb][0], B0));
            int q01 = __float2int_rn(fmaf(A, (float)d[nb][1], B1));
            int q10 = __float2int_rn(fmaf(A, (float)d[nb][2], B0));
            int q11 = __float2int_rn(fmaf(A, (float)d[nb][3], B1));
            *(unsigned short*)&s_y[(px0 + gid) * 68 + nb * 8 + 2 * tig] =
                (unsigned short)pack_u8(q01, q00, 0);
            *(unsigned short*)&s_y[(px0 + gid + 8) * 68 + nb * 8 + 2 * tig] =
                (unsigned short)pack_u8(q11, q10, 0);
        }
        __syncthreads();

        // repack: 128 px x 16 oc4-words -> gmem (coalesced uint4 per thread)
        for (int i = tid; i < 512; i += 256) {
            int oc4l = i >> 5;
            int pxq = (i & 31) * 4;
            if (hw0 + pxq < HW) {
                uint4 v;
                v.x = *(const unsigned*)&s_y[(pxq + 0) * 68 + oc4l * 4];
                v.y = *(const unsigned*)&s_y[(pxq + 1) * 68 + oc4l * 4];
                v.z = *(const unsigned*)&s_y[(pxq + 2) * 68 + oc4l * 4];
                v.w = *(const unsigned*)&s_y[(pxq + 3) * 68 + oc4l * 4];
                *(uint4*)&out[(size_t)(n * COUT4 + (oc0 >> 2) + oc4l) * HW
                              + hw0 + pxq] = v;
            }
        }
    }
}

// ---------------------------------------------------------------------------
// 2x2 maxpool stride 2 (per-byte vmax on u8) + requant to s8.
// ---------------------------------------------------------------------------
__global__ void pool_kernel(const unsigned* __restrict__ in,
                            unsigned* __restrict__ out,
                            int G, int H, int W,
                            const float* __restrict__ scales,
                            int si_in, int si_out) {
    int OH = H >> 1, OW = W >> 1, OW2 = OW >> 1;
    int idx = blockIdx.x * 256 + threadIdx.x;
    int ox = (idx % OW2) * 2;
    int t = idx / OW2;
    int oy = t % OH; t /= OH;
    int g = t % G;
    int n = t / G;

    const unsigned* p = in + ((size_t)(n * G + g) * H + oy * 2) * W + ox * 2;
    uint4 a = *(const uint4*)p;
    uint4 b = *(const uint4*)(p + W);
    unsigned m0 = __vmaxu4(__vmaxu4(a.x, a.y), __vmaxu4(b.x, b.y));
    unsigned m1 = __vmaxu4(__vmaxu4(a.z, a.w), __vmaxu4(b.z, b.w));

    float r = scales[si_in] / scales[si_out];
    uint2 pk;
    unsigned mm[2] = {m0, m1};
    unsigned* pw = &pk.x;
    #pragma unroll
    for (int p2 = 0; p2 < 2; p2++) {
        int q0 = __float2int_rn((float)((mm[p2]) & 0xFF) * r);
        int q1 = __float2int_rn((float)((mm[p2] >> 8) & 0xFF) * r);
        int q2 = __float2int_rn((float)((mm[p2] >> 16) & 0xFF) * r);
        int q3 = __float2int_rn((float)((mm[p2] >> 24) & 0xFF) * r);
        pw[p2] = pack_s8(q1, q0, pack_s8(q3, q2, 0));
    }
    out[((size_t)(n * G + g) * OH + oy) * OW + ox] = pk.x;
    out[((size_t)(n * G + g) * OH + oy) * OW + ox + 1] = pk.y;
}

// ---------------------------------------------------------------------------
// Global avg pool 28x28 (s8 input) + fq(s[11], int8) -> g_gap floats.
// ---------------------------------------------------------------------------
__global__ void gap_kernel(const unsigned* __restrict__ in,
                           const float* __restrict__ scales) {
    __shared__ int4 red[128];
    int bc = blockIdx.x;        // n*64 + g
    const unsigned* p = in + (size_t)bc * 784;
    int s0 = 0, s1 = 0, s2 = 0, s3 = 0;
    for (int i = threadIdx.x; i < 784; i += 128) {
        unsigned v = p[i];
        s0 += (int)(v << 24) >> 24;
        s1 += (int)(v << 16) >> 24;
        s2 += (int)(v << 8) >> 24;
        s3 += (int)v >> 24;
    }
    red[threadIdx.x] = make_int4(s0, s1, s2, s3);
    __syncthreads();
    for (int s = 64; s > 0; s >>= 1) {
        if (threadIdx.x < s) {
            int4 a = red[threadIdx.x], b = red[threadIdx.x + s];
            red[threadIdx.x] = make_int4(a.x + b.x, a.y + b.y, a.z + b.z, a.w + b.w);
        }
        __syncthreads();
    }
    if (threadIdx.x == 0) {
        float s10 = scales[10], s11 = scales[11];
        int4 r = red[0];
        int n = bc >> 6, g = bc & 63;
        int sums[4] = {r.x, r.y, r.z, r.w};
        #pragma unroll
        for (int j = 0; j < 4; j++) {
            float m = s10 * (float)sums[j] / 784.0f;
            g_gap[n * 256 + g * 4 + j] = fqv(m, s11, -128.0f, 127.0f);
        }
    }
}

// ---------------------------------------------------------------------------
// FC: [8,256] @ Wq^T + b -> [8,10]
// ---------------------------------------------------------------------------
__global__ void fc_kernel(const float* __restrict__ fc_b, float* __restrict__ out) {
    int t = threadIdx.x;
    if (t < 80) {
        int n = t / 10, k = t % 10;
        float ws = g_wscale[7];
        float acc = fc_b[k];
        const signed char* w = g_wqi + WQ_FC + k * 256;
        const float* g = g_gap + n * 256;
        #pragma unroll 8
        for (int i = 0; i < 256; i++) acc += (float)w[i] * ws * g[i];
        out[t] = acc;
    }
}

// ---------------------------------------------------------------------------
// Launch
// ---------------------------------------------------------------------------
extern "C" void kernel_launch(void* const* d_in, const int* in_sizes, int n_in,
                              void* d_out, int out_size) {
    const float* x       = (const float*)d_in[0];
    const float* scales  = (const float*)d_in[1];
    const float* conv1_w = (const float*)d_in[2];
    const float* conv1_b = (const float*)d_in[3];
    const float* b1_dw_w = (const float*)d_in[4];
    const float* b1_dw_b = (const float*)d_in[5];
    const float* b1_pw_w = (const float*)d_in[6];
    const float* b1_pw_b = (const float*)d_in[7];
    const float* b2_dw_w = (const float*)d_in[8];
    const float* b2_dw_b = (const float*)d_in[9];
    const float* b2_pw_w = (const float*)d_in[10];
    const float* b2_pw_b = (const float*)d_in[11];
    const float* b3_dw_w = (const float*)d_in[12];
    const float* b3_dw_b = (const float*)d_in[13];
    const float* b3_pw_w = (const float*)d_in[14];
    const float* b3_pw_b = (const float*)d_in[15];
    const float* fc_b    = (const float*)d_in[17];
    float* out = (float*)d_out;

    unsigned *pA = nullptr, *pB = nullptr;
    cudaGetSymbolAddress((void**)&pA, g_bufA);
    cudaGetSymbolAddress((void**)&pB, g_bufB);

    // 1) quantize weights (int8 arena + packed + scales)
    wq_kernel<<<8, 256>>>(conv1_w, b1_dw_w, b1_pw_w, b2_dw_w,
                          b2_pw_w, b3_dw_w, b3_pw_w, (const float*)d_in[16]);

    // 2) conv1 (fused input fq) -> A (u8, 16 groups @224x224)
    {
        dim3 cb(8, 32), cg(7, 7, 8);
        conv1_kernel<<<cg, cb>>>(x, conv1_b, scales, pA);
    }

    // block 1 @ 224x224, C=64 (G=16)
    dw_kernel<false><<<6272, 256, 16 * 24 * 4>>>(pA, pB, WP_B1DW, b1_dw_b,
                                                 16, 224, 224, scales, 1, 2, 1);
    pw_kernel<64, 64><<<dim3(392, 8), 256>>>(pB, pA, WP_B1PW, b1_pw_b,
                                             50176, scales, 2, 3, 2);
    pool_kernel<<<3136, 256>>>(pA, pB, 16, 224, 224, scales, 3, 4);

    // block 2 @ 112x112, 64 -> 128
    dw_kernel<true><<<1568, 256, 16 * 24 * 4>>>(pB, pA, WP_B2DW, b2_dw_b,
                                                16, 112, 112, scales, 4, 5, 3);
    pw_kernel<64, 128><<<dim3(98, 8), 256>>>(pA, pB, WP_B2PW, b2_pw_b,
                                             12544, scales, 5, 6, 4);
    pool_kernel<<<1568, 256>>>(pB, pA, 32, 112, 112, scales, 6, 7);

    // block 3 @ 56x56, 128 -> 256
    dw_kernel<true><<<784, 256, 32 * 24 * 4>>>(pA, pB, WP_B3DW, b3_dw_b,
                                               32, 56, 56, scales, 7, 8, 5);
    pw_kernel<128, 256><<<dim3(25, 8), 256>>>(pB, pA, WP_B3PW, b3_pw_b,
                                              3136, scales, 8, 9, 6);
    pool_kernel<<<784, 256>>>(pA, pB, 64, 56, 56, scales, 9, 10);

    // head
    gap_kernel<<<512, 128>>>(pB, scales);
    fc_kernel<<<1, 128>>>(fc_b, out);
}